// round 7
// baseline (speedup 1.0000x reference)
#include <cuda_runtime.h>
#include <cuda_fp16.h>
#include <math.h>
#include <stdint.h>

// ContinuousRelativePositionalBias — Round 7: R5 shape (8 warps, 64x64 warp
// tiles, 256-pt iter) + crossbar diet:
//  * gen_h1 blocked 8p x 16c with packed W1 float4 -> 24 LDS + 16 STS per thread
//  * epilogue n8-outer, params loaded once -> 24 LDS per thread
//  * B-fragment double buffer across k-loop (prefetch kc+1)
//  * red double-buffered -> ONE __syncthreads per iteration

#define ID 512
#define JD 512
#define DD 128
#define MROWS 256
#define NTHREADS 256
#define GRIDSZ 148
#define NITER 4096

#define SWZ(row, chunk) ((unsigned)(row) * 256u + ((((unsigned)(chunk)) ^ ((unsigned)(row) & 7u)) << 4))

// smem byte offsets
#define OFF_W2    0          // 32KB fp16 W2^T [n][k] swizzled
#define OFF_H1A   32768      // 64KB
#define OFF_H1B   98304      // 64KB
#define OFF_RED   163840     // 2 x 8KB (double-buffered)
#define OFF_BIASA 180224     // 256 float4
#define OFF_BIASB 184320     // 256 float4
#define OFF_W1P   188416     // 128 float4 {w0,w1,w2,b1}
#define OFF_B2    190464     // 128 floats
#define OFF_W3    190976     // 512 floats [e][o]
#define OFF_B3    193024     // 4 floats
#define SMEM_BYTES 193088

__device__ __align__(16) uint8_t g_w2h[32768];

__global__ void prep_w2(const float* __restrict__ W2) {
    int idx = blockIdx.x * blockDim.x + threadIdx.x;
    if (idx >= DD * DD) return;
    int n = idx >> 7, k = idx & 127;
    unsigned byte = SWZ(n, k >> 3) + (unsigned)(k & 7) * 2u;
    *(uint16_t*)(g_w2h + byte) = __half_as_ushort(__float2half_rn(W2[k * DD + n]));
}

__device__ __forceinline__ uint32_t smem_u32(const void* p) {
    uint32_t a;
    asm("{ .reg .u64 t; cvta.to.shared.u64 t, %1; cvt.u32.u64 %0, t; }" : "=r"(a) : "l"(p));
    return a;
}
__device__ __forceinline__ void ldsm_x4(uint32_t* r, uint32_t addr) {
    asm volatile("ldmatrix.sync.aligned.m8n8.x4.shared.b16 {%0,%1,%2,%3}, [%4];"
                 : "=r"(r[0]), "=r"(r[1]), "=r"(r[2]), "=r"(r[3]) : "r"(addr));
}
__device__ __forceinline__ void mma_fp16(float* c, const uint32_t* a, uint32_t b0, uint32_t b1) {
    asm volatile("mma.sync.aligned.m16n8k16.row.col.f32.f16.f16.f32 "
                 "{%0,%1,%2,%3}, {%4,%5,%6,%7}, {%8,%9}, {%0,%1,%2,%3};"
                 : "+f"(c[0]), "+f"(c[1]), "+f"(c[2]), "+f"(c[3])
                 : "r"(a[0]), "r"(a[1]), "r"(a[2]), "r"(a[3]), "r"(b0), "r"(b1));
}
#define CP_ASYNC16(dst, src) \
    asm volatile("cp.async.cg.shared.global [%0], [%1], 16;" :: "r"(dst), "l"(src) : "memory")
#define CP_ASYNC_COMMIT() asm volatile("cp.async.commit_group;" ::: "memory")
#define CP_ASYNC_WAIT0()  asm volatile("cp.async.wait_group 0;" ::: "memory")

// ---------------- pipeline stages ----------------
__device__ __forceinline__ void compute_bias(int it, float4* sB4,
                                             const float* __restrict__ grid_q,
                                             const float* __restrict__ grid_kv, int tid) {
    const int pair = it & 1;
    const int i    = (it >> 1) & (ID - 1);
    const int b    = it >> 10;
    const int j    = pair * MROWS + tid;
    const float q0 = __ldg(grid_q + i * 3 + 0);
    const float q1 = __ldg(grid_q + i * 3 + 1);
    const float q2 = __ldg(grid_q + i * 3 + 2);
    const float p0 = q0 - grid_kv[(b * JD + j) * 3 + 0];
    const float p1 = q1 - grid_kv[(b * JD + j) * 3 + 1];
    const float p2 = q2 - grid_kv[(b * JD + j) * 3 + 2];
    sB4[tid] = make_float4(copysignf(__logf(1.0f + fabsf(p0)), p0),
                           copysignf(__logf(1.0f + fabsf(p1)), p1),
                           copysignf(__logf(1.0f + fabsf(p2)), p2), 0.0f);
}

// blocked gen: thread = 8 points x 16 cols. 24 LDS.128 + 16 STS.128.
__device__ __forceinline__ void gen_h1(const float4* __restrict__ sB4,
                                       const float4* __restrict__ sW1p,
                                       char* hbuf, int tid) {
    const int pb = tid >> 3;        // 0..31 -> points pb*8..+7
    const int cb = tid & 7;         // 0..7  -> cols cb*16..+15
    const int p0 = pb * 8;
    const int d0 = cb * 16;
    float4 w[16];
    #pragma unroll
    for (int q = 0; q < 16; ++q) w[q] = sW1p[d0 + q];
    #pragma unroll
    for (int pp = 0; pp < 8; ++pp) {
        const float4 bs = sB4[p0 + pp];
        uint32_t hv[8];
        #pragma unroll
        for (int q = 0; q < 8; ++q) {
            float h0 = fmaxf(fmaf(bs.x, w[2*q].x,   fmaf(bs.y, w[2*q].y,   fmaf(bs.z, w[2*q].z,   w[2*q].w))),   0.0f);
            float h1 = fmaxf(fmaf(bs.x, w[2*q+1].x, fmaf(bs.y, w[2*q+1].y, fmaf(bs.z, w[2*q+1].z, w[2*q+1].w))), 0.0f);
            __half2 hh = __floats2half2_rn(h0, h1);
            hv[q] = *(uint32_t*)&hh;
        }
        *(uint4*)(hbuf + SWZ(p0 + pp, cb * 2))     = make_uint4(hv[0], hv[1], hv[2], hv[3]);
        *(uint4*)(hbuf + SWZ(p0 + pp, cb * 2 + 1)) = make_uint4(hv[4], hv[5], hv[6], hv[7]);
    }
}

// ---------------- main persistent kernel ----------------
__global__ __launch_bounds__(NTHREADS, 1)
void crpb_kernel(const float* __restrict__ grid_q,
                 const float* __restrict__ grid_kv,
                 const float* __restrict__ W1, const float* __restrict__ b1,
                 const float* __restrict__ b2,
                 const float* __restrict__ W3, const float* __restrict__ b3,
                 float* __restrict__ out)
{
    extern __shared__ __align__(1024) char smem[];
    float4* sW1p   = (float4*)(smem + OFF_W1P);
    float*  sb2    = (float*)(smem + OFF_B2);
    float*  sW3    = (float*)(smem + OFF_W3);
    float*  sb3    = (float*)(smem + OFF_B3);
    float4* sBiasA = (float4*)(smem + OFF_BIASA);
    float4* sBiasB = (float4*)(smem + OFF_BIASB);

    const int tid  = threadIdx.x;
    const int lane = tid & 31;
    const int wid  = tid >> 5;

    // ---- one-time prologue ----
    if (tid < DD) {
        sW1p[tid] = make_float4(W1[tid], W1[DD + tid], W1[2 * DD + tid], b1[tid]);
        sb2[tid]  = b2[tid];
        reinterpret_cast<float4*>(sW3)[tid] = reinterpret_cast<const float4*>(W3)[tid];
    }
    if (tid < 4) sb3[tid] = b3[tid];
    {
        uint32_t dst = smem_u32(smem + OFF_W2) + tid * 16;
        const char* src = (const char*)g_w2h + tid * 16;
        #pragma unroll
        for (int it = 0; it < 8; ++it) CP_ASYNC16(dst + it * 4096, src + it * 4096);
        CP_ASYNC_COMMIT();
    }

    const int nt = (NITER - blockIdx.x + GRIDSZ - 1) / GRIDSZ;
    #define TILE_AT(k) (blockIdx.x + (k) * GRIDSZ)

    compute_bias(TILE_AT(0), sBiasA, grid_q, grid_kv, tid);
    if (nt > 1) compute_bias(TILE_AT(1), sBiasB, grid_q, grid_kv, tid);
    CP_ASYNC_WAIT0();
    __syncthreads();
    gen_h1(sBiasA, sW1p, smem + OFF_H1A, tid);
    __syncthreads();

    // GEMM invariants: 8 warps = 4(wm) x 2(wn); warp tile 64M x 64N
    const int wm = wid & 3;
    const int wn = wid >> 2;
    const int arow = wm * 64 + (lane & 15);
    const unsigned asel = lane >> 4;
    const int brow = wn * 64 + (lane & 7) + ((lane >> 4) << 3);
    const unsigned bsel = (lane >> 3) & 1;
    const int g  = lane >> 2;
    const int t4 = lane & 3;
    const uint32_t w2b = smem_u32(smem + OFF_W2);

    for (int k = 0; k < nt; ++k) {
        if (k + 2 < nt)
            compute_bias(TILE_AT(k + 2), (k & 1) ? sBiasB : sBiasA, grid_q, grid_kv, tid);
        if (k + 1 < nt)
            gen_h1((k & 1) ? sBiasA : sBiasB, sW1p,
                   smem + (((k + 1) & 1) ? OFF_H1B : OFF_H1A), tid);

        // ---- GEMM: H1[256,128] @ W2[128,128], B double-buffered ----
        const uint32_t h1b = smem_u32(smem + ((k & 1) ? OFF_H1B : OFF_H1A));
        float acc[4][8][4];
        #pragma unroll
        for (int mt = 0; mt < 4; ++mt)
            #pragma unroll
            for (int n8 = 0; n8 < 8; ++n8)
                #pragma unroll
                for (int c = 0; c < 4; ++c) acc[mt][n8][c] = 0.0f;

        uint32_t Bf[2][4][4];
        #pragma unroll
        for (int ng = 0; ng < 4; ++ng)
            ldsm_x4(Bf[0][ng], w2b + SWZ(brow + ng * 16, bsel));

        #pragma unroll
        for (int kc = 0; kc < 8; ++kc) {
            const int cur = kc & 1, nxt = cur ^ 1;
            uint32_t A[4][4];
            #pragma unroll
            for (int mt = 0; mt < 4; ++mt)
                ldsm_x4(A[mt], h1b + SWZ(arow + mt * 16, kc * 2 + asel));
            if (kc < 7) {
                #pragma unroll
                for (int ng = 0; ng < 4; ++ng)
                    ldsm_x4(Bf[nxt][ng], w2b + SWZ(brow + ng * 16, (kc + 1) * 2 + bsel));
            }
            #pragma unroll
            for (int mt = 0; mt < 4; ++mt)
                #pragma unroll
                for (int ng = 0; ng < 4; ++ng) {
                    mma_fp16(acc[mt][2 * ng],     A[mt], Bf[cur][ng][0], Bf[cur][ng][1]);
                    mma_fp16(acc[mt][2 * ng + 1], A[mt], Bf[cur][ng][2], Bf[cur][ng][3]);
                }
        }

        // ---- epilogue: relu(H2+b2) @ W3, n8-outer (params loaded once) ----
        float4* redc = (float4*)(smem + OFF_RED) + (k & 1) * 512;
        float ov[4][2][4];
        #pragma unroll
        for (int mt = 0; mt < 4; ++mt)
            #pragma unroll
            for (int h = 0; h < 2; ++h)
                #pragma unroll
                for (int o = 0; o < 4; ++o) ov[mt][h][o] = 0.0f;

        #pragma unroll
        for (int n8 = 0; n8 < 8; ++n8) {
            const int e0 = wn * 64 + n8 * 8 + 2 * t4;
            const float2 b2v = *(const float2*)(sb2 + e0);
            const float4 w30 = *(const float4*)(sW3 + e0 * 4);
            const float4 w31 = *(const float4*)(sW3 + (e0 + 1) * 4);
            #pragma unroll
            for (int mt = 0; mt < 4; ++mt) {
                float h00 = fmaxf(acc[mt][n8][0] + b2v.x, 0.0f);
                float h01 = fmaxf(acc[mt][n8][1] + b2v.y, 0.0f);
                float h10 = fmaxf(acc[mt][n8][2] + b2v.x, 0.0f);
                float h11 = fmaxf(acc[mt][n8][3] + b2v.y, 0.0f);
                ov[mt][0][0] = fmaf(h00, w30.x, fmaf(h01, w31.x, ov[mt][0][0]));
                ov[mt][0][1] = fmaf(h00, w30.y, fmaf(h01, w31.y, ov[mt][0][1]));
                ov[mt][0][2] = fmaf(h00, w30.z, fmaf(h01, w31.z, ov[mt][0][2]));
                ov[mt][0][3] = fmaf(h00, w30.w, fmaf(h01, w31.w, ov[mt][0][3]));
                ov[mt][1][0] = fmaf(h10, w30.x, fmaf(h11, w31.x, ov[mt][1][0]));
                ov[mt][1][1] = fmaf(h10, w30.y, fmaf(h11, w31.y, ov[mt][1][1]));
                ov[mt][1][2] = fmaf(h10, w30.z, fmaf(h11, w31.z, ov[mt][1][2]));
                ov[mt][1][3] = fmaf(h10, w30.w, fmaf(h11, w31.w, ov[mt][1][3]));
            }
        }
        #pragma unroll
        for (int mt = 0; mt < 4; ++mt) {
            #pragma unroll
            for (int h = 0; h < 2; ++h)
                #pragma unroll
                for (int o = 0; o < 4; ++o) {
                    float v = ov[mt][h][o];
                    v += __shfl_xor_sync(0xFFFFFFFF, v, 1);
                    v += __shfl_xor_sync(0xFFFFFFFF, v, 2);
                    ov[mt][h][o] = v;
                }
            if (t4 == 0) {
                redc[wn * 256 + wm * 64 + mt * 16 + g]     = make_float4(ov[mt][0][0], ov[mt][0][1], ov[mt][0][2], ov[mt][0][3]);
                redc[wn * 256 + wm * 64 + mt * 16 + 8 + g] = make_float4(ov[mt][1][0], ov[mt][1][1], ov[mt][1][2], ov[mt][1][3]);
            }
        }
        __syncthreads();   // the ONLY barrier per iteration

        {
            const float4 r0 = redc[tid];
            const float4 r1 = redc[256 + tid];
            const int it = TILE_AT(k);
            const int pair = it & 1;
            const int i    = (it >> 1) & (ID - 1);
            const int b    = it >> 10;
            const long base = ((long)(b * 4) * ID + i) * JD + pair * MROWS + tid;
            const long os   = (long)ID * JD;
            out[base]          = r0.x + r1.x + sb3[0];
            out[base + os]     = r0.y + r1.y + sb3[1];
            out[base + 2 * os] = r0.z + r1.z + sb3[2];
            out[base + 3 * os] = r0.w + r1.w + sb3[3];
        }
    }
}

extern "C" void kernel_launch(void* const* d_in, const int* in_sizes, int n_in,
                              void* d_out, int out_size)
{
    const float* grid_q  = (const float*)d_in[0];
    const float* grid_kv = (const float*)d_in[1];
    const float* W1      = (const float*)d_in[2];
    const float* b1      = (const float*)d_in[3];
    const float* W2      = (const float*)d_in[4];
    const float* b2      = (const float*)d_in[5];
    const float* W3      = (const float*)d_in[6];
    const float* b3      = (const float*)d_in[7];
    float* out = (float*)d_out;

    prep_w2<<<DD * DD / 256, 256>>>(W2);

    cudaFuncSetAttribute(crpb_kernel,
                         cudaFuncAttributeMaxDynamicSharedMemorySize, SMEM_BYTES);
    crpb_kernel<<<GRIDSZ, NTHREADS, SMEM_BYTES>>>(
        grid_q, grid_kv, W1, b1, b2, W3, b3, out);
}

// round 8
// speedup vs baseline: 1.4887x; 1.4887x over previous
#include <cuda_runtime.h>
#include <cuda_fp16.h>
#include <math.h>
#include <stdint.h>

// ContinuousRelativePositionalBias — Round 8: R5 economics (64x64 warp tiles,
// MMA/ldsm = 4.0, broadcast-LDS gen, per-mt epilogue) but TWO independent
// 128-thread CTAs per SM (grid 296, __launch_bounds__(128,2)) so one CTA's
// GEMM covers the other's barriers and ldsm->mma latency.

#define ID 512
#define JD 512
#define DD 128
#define MROWS 128            // points per iteration (one j-tile)
#define NTHREADS 128
#define GRIDSZ 296           // 2 x 148
#define NITER 8192           // 4 * 512 * 4

#define SWZ(row, chunk) ((unsigned)(row) * 256u + ((((unsigned)(chunk)) ^ ((unsigned)(row) & 7u)) << 4))

// smem byte offsets
#define OFF_W2    0          // 32KB fp16 W2^T [n][k] swizzled
#define OFF_H1A   32768      // 32KB (128 x 128 fp16)
#define OFF_H1B   65536      // 32KB
#define OFF_RED   98304      // 256 float4 = 4KB
#define OFF_BIASA 102400     // 3*128 floats
#define OFF_BIASB 103936
#define OFF_W1    105472     // 384 floats
#define OFF_B1    107008     // 128
#define OFF_B2    107520     // 128
#define OFF_W3    108032     // 512 floats [e][o]
#define OFF_B3    110080     // 4
#define SMEM_BYTES 110144

__device__ __align__(16) uint8_t g_w2h[32768];

__global__ void prep_w2(const float* __restrict__ W2) {
    int idx = blockIdx.x * blockDim.x + threadIdx.x;
    if (idx >= DD * DD) return;
    int n = idx >> 7, k = idx & 127;
    unsigned byte = SWZ(n, k >> 3) + (unsigned)(k & 7) * 2u;
    *(uint16_t*)(g_w2h + byte) = __half_as_ushort(__float2half_rn(W2[k * DD + n]));
}

__device__ __forceinline__ uint32_t smem_u32(const void* p) {
    uint32_t a;
    asm("{ .reg .u64 t; cvta.to.shared.u64 t, %1; cvt.u32.u64 %0, t; }" : "=r"(a) : "l"(p));
    return a;
}
__device__ __forceinline__ void ldsm_x4(uint32_t* r, uint32_t addr) {
    asm volatile("ldmatrix.sync.aligned.m8n8.x4.shared.b16 {%0,%1,%2,%3}, [%4];"
                 : "=r"(r[0]), "=r"(r[1]), "=r"(r[2]), "=r"(r[3]) : "r"(addr));
}
__device__ __forceinline__ void mma_fp16(float* c, const uint32_t* a, uint32_t b0, uint32_t b1) {
    asm volatile("mma.sync.aligned.m16n8k16.row.col.f32.f16.f16.f32 "
                 "{%0,%1,%2,%3}, {%4,%5,%6,%7}, {%8,%9}, {%0,%1,%2,%3};"
                 : "+f"(c[0]), "+f"(c[1]), "+f"(c[2]), "+f"(c[3])
                 : "r"(a[0]), "r"(a[1]), "r"(a[2]), "r"(a[3]), "r"(b0), "r"(b1));
}
#define CP_ASYNC16(dst, src) \
    asm volatile("cp.async.cg.shared.global [%0], [%1], 16;" :: "r"(dst), "l"(src) : "memory")
#define CP_ASYNC_COMMIT() asm volatile("cp.async.commit_group;" ::: "memory")
#define CP_ASYNC_WAIT0()  asm volatile("cp.async.wait_group 0;" ::: "memory")

// ---------------- pipeline stages ----------------
__device__ __forceinline__ void compute_bias(int it, float* sB,
                                             const float* __restrict__ grid_q,
                                             const float* __restrict__ grid_kv, int tid) {
    const int jt = it & 3;
    const int i  = (it >> 2) & (ID - 1);
    const int b  = it >> 11;
    const int j  = jt * MROWS + tid;
    const float q0 = __ldg(grid_q + i * 3 + 0);
    const float q1 = __ldg(grid_q + i * 3 + 1);
    const float q2 = __ldg(grid_q + i * 3 + 2);
    const float p0 = q0 - grid_kv[(b * JD + j) * 3 + 0];
    const float p1 = q1 - grid_kv[(b * JD + j) * 3 + 1];
    const float p2 = q2 - grid_kv[(b * JD + j) * 3 + 2];
    sB[tid]             = copysignf(__logf(1.0f + fabsf(p0)), p0);
    sB[MROWS + tid]     = copysignf(__logf(1.0f + fabsf(p1)), p1);
    sB[2 * MROWS + tid] = copysignf(__logf(1.0f + fabsf(p2)), p2);
}

// one point per thread; sW1/sb1 reads are uniform broadcasts (cheap)
__device__ __forceinline__ void gen_h1(const float* __restrict__ sB,
                                       const float* __restrict__ sW1,
                                       const float* __restrict__ sb1,
                                       char* hbuf, int tid) {
    const int p = tid;
    const float bs0 = sB[p];
    const float bs1 = sB[MROWS + p];
    const float bs2 = sB[2 * MROWS + p];
    #pragma unroll
    for (int dd = 0; dd < 16; ++dd) {
        const int d0 = dd * 8;
        uint32_t hv[4];
        #pragma unroll
        for (int q = 0; q < 4; ++q) {
            const int d = d0 + 2 * q;
            float h0 = fmaxf(fmaf(bs0, sW1[d],     fmaf(bs1, sW1[DD + d],     fmaf(bs2, sW1[2*DD + d],     sb1[d]))),     0.0f);
            float h1 = fmaxf(fmaf(bs0, sW1[d + 1], fmaf(bs1, sW1[DD + d + 1], fmaf(bs2, sW1[2*DD + d + 1], sb1[d + 1]))), 0.0f);
            __half2 hh = __floats2half2_rn(h0, h1);
            hv[q] = *(uint32_t*)&hh;
        }
        *(uint4*)(hbuf + SWZ(p, dd)) = make_uint4(hv[0], hv[1], hv[2], hv[3]);
    }
}

// ---------------- main persistent kernel ----------------
__global__ __launch_bounds__(NTHREADS, 2)
void crpb_kernel(const float* __restrict__ grid_q,
                 const float* __restrict__ grid_kv,
                 const float* __restrict__ W1, const float* __restrict__ b1,
                 const float* __restrict__ b2,
                 const float* __restrict__ W3, const float* __restrict__ b3,
                 float* __restrict__ out)
{
    extern __shared__ __align__(1024) char smem[];
    float* sW1    = (float*)(smem + OFF_W1);
    float* sb1    = (float*)(smem + OFF_B1);
    float* sb2    = (float*)(smem + OFF_B2);
    float* sW3    = (float*)(smem + OFF_W3);
    float* sb3    = (float*)(smem + OFF_B3);
    float* sBiasA = (float*)(smem + OFF_BIASA);
    float* sBiasB = (float*)(smem + OFF_BIASB);
    float4* red4  = (float4*)(smem + OFF_RED);

    const int tid  = threadIdx.x;
    const int lane = tid & 31;
    const int wid  = tid >> 5;

    // ---- one-time prologue ----
    if (tid < DD) {
        sW1[tid]       = W1[tid];
        sW1[DD + tid]  = W1[DD + tid];
        sW1[2*DD + tid]= W1[2 * DD + tid];
        sb1[tid] = b1[tid];
        sb2[tid] = b2[tid];
        reinterpret_cast<float4*>(sW3)[tid] = reinterpret_cast<const float4*>(W3)[tid];
    }
    if (tid < 4) sb3[tid] = b3[tid];
    {
        uint32_t dst = smem_u32(smem + OFF_W2) + tid * 16;
        const char* src = (const char*)g_w2h + tid * 16;
        #pragma unroll
        for (int it = 0; it < 16; ++it) CP_ASYNC16(dst + it * 2048, src + it * 2048);
        CP_ASYNC_COMMIT();
    }

    const int nt = (NITER - blockIdx.x + GRIDSZ - 1) / GRIDSZ;
    #define TILE_AT(k) (blockIdx.x + (k) * GRIDSZ)

    compute_bias(TILE_AT(0), sBiasA, grid_q, grid_kv, tid);
    if (nt > 1) compute_bias(TILE_AT(1), sBiasB, grid_q, grid_kv, tid);
    CP_ASYNC_WAIT0();
    __syncthreads();
    gen_h1(sBiasA, sW1, sb1, smem + OFF_H1A, tid);
    __syncthreads();

    // GEMM invariants: 4 warps = 2(wm) x 2(wn); warp tile 64M x 64N
    const int wm = wid & 1;
    const int wn = wid >> 1;
    const int arow = wm * 64 + (lane & 15);
    const unsigned asel = lane >> 4;
    const int brow = wn * 64 + (lane & 7) + ((lane >> 4) << 3);
    const unsigned bsel = (lane >> 3) & 1;
    const int g  = lane >> 2;
    const int t4 = lane & 3;
    const uint32_t w2b = smem_u32(smem + OFF_W2);

    for (int k = 0; k < nt; ++k) {
        if (k + 2 < nt)
            compute_bias(TILE_AT(k + 2), (k & 1) ? sBiasB : sBiasA, grid_q, grid_kv, tid);
        if (k + 1 < nt)
            gen_h1((k & 1) ? sBiasA : sBiasB, sW1, sb1,
                   smem + (((k + 1) & 1) ? OFF_H1B : OFF_H1A), tid);

        // ---- GEMM: H1[128,128] @ W2[128,128] ----
        const uint32_t h1b = smem_u32(smem + ((k & 1) ? OFF_H1B : OFF_H1A));
        float acc[4][8][4];
        #pragma unroll
        for (int mt = 0; mt < 4; ++mt)
            #pragma unroll
            for (int n8 = 0; n8 < 8; ++n8)
                #pragma unroll
                for (int c = 0; c < 4; ++c) acc[mt][n8][c] = 0.0f;

        #pragma unroll
        for (int kc = 0; kc < 8; ++kc) {
            uint32_t A[4][4], Bf[4][4];
            #pragma unroll
            for (int mt = 0; mt < 4; ++mt)
                ldsm_x4(A[mt], h1b + SWZ(arow + mt * 16, kc * 2 + asel));
            #pragma unroll
            for (int ng = 0; ng < 4; ++ng)
                ldsm_x4(Bf[ng], w2b + SWZ(brow + ng * 16, kc * 2 + bsel));
            #pragma unroll
            for (int mt = 0; mt < 4; ++mt)
                #pragma unroll
                for (int ng = 0; ng < 4; ++ng) {
                    mma_fp16(acc[mt][2 * ng],     A[mt], Bf[ng][0], Bf[ng][1]);
                    mma_fp16(acc[mt][2 * ng + 1], A[mt], Bf[ng][2], Bf[ng][3]);
                }
        }

        // ---- epilogue: relu(H2+b2) @ W3, per mt (low live regs) ----
        #pragma unroll
        for (int mt = 0; mt < 4; ++mt) {
            float ov[2][4] = {{0,0,0,0},{0,0,0,0}};
            #pragma unroll
            for (int n8 = 0; n8 < 8; ++n8) {
                const int e0 = wn * 64 + n8 * 8 + 2 * t4;
                float2 b2v = *(const float2*)(sb2 + e0);
                float4 w30 = *(const float4*)(sW3 + e0 * 4);
                float4 w31 = *(const float4*)(sW3 + (e0 + 1) * 4);
                float h00 = fmaxf(acc[mt][n8][0] + b2v.x, 0.0f);
                float h01 = fmaxf(acc[mt][n8][1] + b2v.y, 0.0f);
                float h10 = fmaxf(acc[mt][n8][2] + b2v.x, 0.0f);
                float h11 = fmaxf(acc[mt][n8][3] + b2v.y, 0.0f);
                ov[0][0] = fmaf(h00, w30.x, fmaf(h01, w31.x, ov[0][0]));
                ov[0][1] = fmaf(h00, w30.y, fmaf(h01, w31.y, ov[0][1]));
                ov[0][2] = fmaf(h00, w30.z, fmaf(h01, w31.z, ov[0][2]));
                ov[0][3] = fmaf(h00, w30.w, fmaf(h01, w31.w, ov[0][3]));
                ov[1][0] = fmaf(h10, w30.x, fmaf(h11, w31.x, ov[1][0]));
                ov[1][1] = fmaf(h10, w30.y, fmaf(h11, w31.y, ov[1][1]));
                ov[1][2] = fmaf(h10, w30.z, fmaf(h11, w31.z, ov[1][2]));
                ov[1][3] = fmaf(h10, w30.w, fmaf(h11, w31.w, ov[1][3]));
            }
            #pragma unroll
            for (int h = 0; h < 2; ++h)
                #pragma unroll
                for (int o = 0; o < 4; ++o) {
                    float v = ov[h][o];
                    v += __shfl_xor_sync(0xFFFFFFFF, v, 1);
                    v += __shfl_xor_sync(0xFFFFFFFF, v, 2);
                    ov[h][o] = v;
                }
            if (t4 == 0) {
                red4[wn * 128 + wm * 64 + mt * 16 + g]     = make_float4(ov[0][0], ov[0][1], ov[0][2], ov[0][3]);
                red4[wn * 128 + wm * 64 + mt * 16 + 8 + g] = make_float4(ov[1][0], ov[1][1], ov[1][2], ov[1][3]);
            }
        }
        __syncthreads();

        {
            const float4 r0 = red4[tid];
            const float4 r1 = red4[128 + tid];
            const int it = TILE_AT(k);
            const int jt = it & 3;
            const int i  = (it >> 2) & (ID - 1);
            const int b  = it >> 11;
            const long base = ((long)(b * 4) * ID + i) * JD + jt * MROWS + tid;
            const long os   = (long)ID * JD;
            out[base]          = r0.x + r1.x + sb3[0];
            out[base + os]     = r0.y + r1.y + sb3[1];
            out[base + 2 * os] = r0.z + r1.z + sb3[2];
            out[base + 3 * os] = r0.w + r1.w + sb3[3];
        }
        __syncthreads();
    }
}

extern "C" void kernel_launch(void* const* d_in, const int* in_sizes, int n_in,
                              void* d_out, int out_size)
{
    const float* grid_q  = (const float*)d_in[0];
    const float* grid_kv = (const float*)d_in[1];
    const float* W1      = (const float*)d_in[2];
    const float* b1      = (const float*)d_in[3];
    const float* W2      = (const float*)d_in[4];
    const float* b2      = (const float*)d_in[5];
    const float* W3      = (const float*)d_in[6];
    const float* b3      = (const float*)d_in[7];
    float* out = (float*)d_out;

    prep_w2<<<DD * DD / 256, 256>>>(W2);

    cudaFuncSetAttribute(crpb_kernel,
                         cudaFuncAttributeMaxDynamicSharedMemorySize, SMEM_BYTES);
    crpb_kernel<<<GRIDSZ, NTHREADS, SMEM_BYTES>>>(
        grid_q, grid_kv, W1, b1, b2, W3, b3, out);
}

// round 9
// speedup vs baseline: 1.5921x; 1.0694x over previous
#include <cuda_runtime.h>
#include <cuda_fp16.h>
#include <math.h>
#include <stdint.h>

// ContinuousRelativePositionalBias — Round 9: A-side smem traffic eliminated.
// A fragments (H1) are computed directly in mma register layout (warp tile
// 32M x 128N, warp grid 4x1): no H1 smem buffers, no gen STS, no A-ldsm.
// B (W2^T, iteration-invariant) remains the only ldsm user. 1 barrier/iter.
// 2 independent 128-thread CTAs per SM (R8's win, kept).

#define ID 512
#define JD 512
#define DD 128
#define MROWS 128
#define NTHREADS 128
#define GRIDSZ 296
#define NITER 8192

#define SWZ(row, chunk) ((unsigned)(row) * 256u + ((((unsigned)(chunk)) ^ ((unsigned)(row) & 7u)) << 4))

// smem byte offsets
#define OFF_W2    0          // 32KB fp16 W2^T [n][k] swizzled
#define OFF_RED   32768      // 2 x 128 float4 = 4KB (double-buffered)
#define OFF_BIAS  36864      // 2 x 128 float4 = 4KB (double-buffered)
#define OFF_W1P   40960      // 128 float4 {w0,w1,w2,b1}
#define OFF_B2    43008      // 128 floats
#define OFF_W3    43520      // 512 floats [e][o]
#define OFF_B3    45568      // 4 floats
#define SMEM_BYTES 45600

__device__ __align__(16) uint8_t g_w2h[32768];

__global__ void prep_w2(const float* __restrict__ W2) {
    int idx = blockIdx.x * blockDim.x + threadIdx.x;
    if (idx >= DD * DD) return;
    int n = idx >> 7, k = idx & 127;
    unsigned byte = SWZ(n, k >> 3) + (unsigned)(k & 7) * 2u;
    *(uint16_t*)(g_w2h + byte) = __half_as_ushort(__float2half_rn(W2[k * DD + n]));
}

__device__ __forceinline__ uint32_t smem_u32(const void* p) {
    uint32_t a;
    asm("{ .reg .u64 t; cvta.to.shared.u64 t, %1; cvt.u32.u64 %0, t; }" : "=r"(a) : "l"(p));
    return a;
}
__device__ __forceinline__ void ldsm_x4(uint32_t* r, uint32_t addr) {
    asm volatile("ldmatrix.sync.aligned.m8n8.x4.shared.b16 {%0,%1,%2,%3}, [%4];"
                 : "=r"(r[0]), "=r"(r[1]), "=r"(r[2]), "=r"(r[3]) : "r"(addr));
}
__device__ __forceinline__ void mma_fp16(float* c, const uint32_t* a, uint32_t b0, uint32_t b1) {
    asm volatile("mma.sync.aligned.m16n8k16.row.col.f32.f16.f16.f32 "
                 "{%0,%1,%2,%3}, {%4,%5,%6,%7}, {%8,%9}, {%0,%1,%2,%3};"
                 : "+f"(c[0]), "+f"(c[1]), "+f"(c[2]), "+f"(c[3])
                 : "r"(a[0]), "r"(a[1]), "r"(a[2]), "r"(a[3]), "r"(b0), "r"(b1));
}
#define CP_ASYNC16(dst, src) \
    asm volatile("cp.async.cg.shared.global [%0], [%1], 16;" :: "r"(dst), "l"(src) : "memory")
#define CP_ASYNC_COMMIT() asm volatile("cp.async.commit_group;" ::: "memory")
#define CP_ASYNC_WAIT0()  asm volatile("cp.async.wait_group 0;" ::: "memory")

__device__ __forceinline__ float relu3(const float4 bs, const float4 w) {
    return fmaxf(fmaf(bs.x, w.x, fmaf(bs.y, w.y, fmaf(bs.z, w.z, w.w))), 0.0f);
}
__device__ __forceinline__ uint32_t h2pack(float a, float b) {
    __half2 h = __floats2half2_rn(a, b);
    return *(uint32_t*)&h;
}

__device__ __forceinline__ void compute_bias(int it, float4* sB4,
                                             const float* __restrict__ grid_q,
                                             const float* __restrict__ grid_kv, int tid) {
    const int jt = it & 3;
    const int i  = (it >> 2) & (ID - 1);
    const int b  = it >> 11;
    const int j  = jt * MROWS + tid;
    const float q0 = __ldg(grid_q + i * 3 + 0);
    const float q1 = __ldg(grid_q + i * 3 + 1);
    const float q2 = __ldg(grid_q + i * 3 + 2);
    const float p0 = q0 - grid_kv[(b * JD + j) * 3 + 0];
    const float p1 = q1 - grid_kv[(b * JD + j) * 3 + 1];
    const float p2 = q2 - grid_kv[(b * JD + j) * 3 + 2];
    sB4[tid] = make_float4(copysignf(__logf(1.0f + fabsf(p0)), p0),
                           copysignf(__logf(1.0f + fabsf(p1)), p1),
                           copysignf(__logf(1.0f + fabsf(p2)), p2), 0.0f);
}

// ---------------- main persistent kernel ----------------
__global__ __launch_bounds__(NTHREADS, 2)
void crpb_kernel(const float* __restrict__ grid_q,
                 const float* __restrict__ grid_kv,
                 const float* __restrict__ W1, const float* __restrict__ b1,
                 const float* __restrict__ b2,
                 const float* __restrict__ W3, const float* __restrict__ b3,
                 float* __restrict__ out)
{
    extern __shared__ __align__(1024) char smem[];
    float4* sW1p  = (float4*)(smem + OFF_W1P);
    float*  sb2   = (float*)(smem + OFF_B2);
    float*  sW3   = (float*)(smem + OFF_W3);
    float*  sb3   = (float*)(smem + OFF_B3);
    float4* sBias = (float4*)(smem + OFF_BIAS);   // 2 x 128
    float4* sRed  = (float4*)(smem + OFF_RED);    // 2 x 128

    const int tid  = threadIdx.x;
    const int lane = tid & 31;
    const int wid  = tid >> 5;         // wm: 4 warps stacked in M

    // ---- one-time prologue ----
    if (tid < DD) {
        sW1p[tid] = make_float4(W1[tid], W1[DD + tid], W1[2 * DD + tid], b1[tid]);
        sb2[tid]  = b2[tid];
        reinterpret_cast<float4*>(sW3)[tid] = reinterpret_cast<const float4*>(W3)[tid];
    }
    if (tid < 4) sb3[tid] = b3[tid];
    {
        uint32_t dst = smem_u32(smem + OFF_W2) + tid * 16;
        const char* src = (const char*)g_w2h + tid * 16;
        #pragma unroll
        for (int it = 0; it < 16; ++it) CP_ASYNC16(dst + it * 2048, src + it * 2048);
        CP_ASYNC_COMMIT();
    }

    const int nt = (NITER - blockIdx.x + GRIDSZ - 1) / GRIDSZ;
    #define TILE_AT(k) (blockIdx.x + (k) * GRIDSZ)

    compute_bias(TILE_AT(0), sBias, grid_q, grid_kv, tid);
    CP_ASYNC_WAIT0();
    __syncthreads();

    const int g  = lane >> 2;
    const int t4 = lane & 3;
    const int brow_base = (lane & 7) + ((lane >> 4) << 3);
    const unsigned bsel = (lane >> 3) & 1;
    const uint32_t w2b = smem_u32(smem + OFF_W2);

    for (int k = 0; k < nt; ++k) {
        const float4* bcur = sBias + (k & 1) * 128;
        if (k + 1 < nt)
            compute_bias(TILE_AT(k + 1), sBias + ((k + 1) & 1) * 128, grid_q, grid_kv, tid);

        // bias rows for this warp's 32 rows (broadcast-friendly LDS)
        const float4 bsr0 = bcur[wid * 32 + g];          // mt0, row g
        const float4 bsr1 = bcur[wid * 32 + 8 + g];      // mt0, row g+8
        const float4 bsr2 = bcur[wid * 32 + 16 + g];     // mt1, row g
        const float4 bsr3 = bcur[wid * 32 + 24 + g];     // mt1, row g+8

        float acc[2][16][4];
        #pragma unroll
        for (int mt = 0; mt < 2; ++mt)
            #pragma unroll
            for (int n8 = 0; n8 < 16; ++n8)
                #pragma unroll
                for (int c = 0; c < 4; ++c) acc[mt][n8][c] = 0.0f;

        #pragma unroll
        for (int kc = 0; kc < 8; ++kc) {
            // W1 columns for this lane's fragment cols (broadcast LDS)
            const int c0 = kc * 16 + 2 * t4;
            const float4 w0 = sW1p[c0];
            const float4 w1 = sW1p[c0 + 1];
            const float4 w8 = sW1p[c0 + 8];
            const float4 w9 = sW1p[c0 + 9];

            // A fragments computed in-register (exact mma layout)
            uint32_t A[2][4];
            A[0][0] = h2pack(relu3(bsr0, w0), relu3(bsr0, w1));
            A[0][1] = h2pack(relu3(bsr1, w0), relu3(bsr1, w1));
            A[0][2] = h2pack(relu3(bsr0, w8), relu3(bsr0, w9));
            A[0][3] = h2pack(relu3(bsr1, w8), relu3(bsr1, w9));
            A[1][0] = h2pack(relu3(bsr2, w0), relu3(bsr2, w1));
            A[1][1] = h2pack(relu3(bsr3, w0), relu3(bsr3, w1));
            A[1][2] = h2pack(relu3(bsr2, w8), relu3(bsr2, w9));
            A[1][3] = h2pack(relu3(bsr3, w8), relu3(bsr3, w9));

            #pragma unroll
            for (int ng = 0; ng < 8; ++ng) {
                uint32_t B[4];
                ldsm_x4(B, w2b + SWZ(ng * 16 + brow_base, kc * 2 + bsel));
                mma_fp16(acc[0][2 * ng],     A[0], B[0], B[1]);
                mma_fp16(acc[0][2 * ng + 1], A[0], B[2], B[3]);
                mma_fp16(acc[1][2 * ng],     A[1], B[0], B[1]);
                mma_fp16(acc[1][2 * ng + 1], A[1], B[2], B[3]);
            }
        }

        // ---- epilogue: relu(H2+b2) @ W3; each warp completes its 32 rows ----
        float4* redc = sRed + (k & 1) * 128;
        #pragma unroll
        for (int mt = 0; mt < 2; ++mt) {
            float ov[2][4] = {{0,0,0,0},{0,0,0,0}};
            #pragma unroll
            for (int n8 = 0; n8 < 16; ++n8) {
                const int e0 = n8 * 8 + 2 * t4;
                const float2 b2v = *(const float2*)(sb2 + e0);
                const float4 w30 = *(const float4*)(sW3 + e0 * 4);
                const float4 w31 = *(const float4*)(sW3 + (e0 + 1) * 4);
                float h00 = fmaxf(acc[mt][n8][0] + b2v.x, 0.0f);
                float h01 = fmaxf(acc[mt][n8][1] + b2v.y, 0.0f);
                float h10 = fmaxf(acc[mt][n8][2] + b2v.x, 0.0f);
                float h11 = fmaxf(acc[mt][n8][3] + b2v.y, 0.0f);
                ov[0][0] = fmaf(h00, w30.x, fmaf(h01, w31.x, ov[0][0]));
                ov[0][1] = fmaf(h00, w30.y, fmaf(h01, w31.y, ov[0][1]));
                ov[0][2] = fmaf(h00, w30.z, fmaf(h01, w31.z, ov[0][2]));
                ov[0][3] = fmaf(h00, w30.w, fmaf(h01, w31.w, ov[0][3]));
                ov[1][0] = fmaf(h10, w30.x, fmaf(h11, w31.x, ov[1][0]));
                ov[1][1] = fmaf(h10, w30.y, fmaf(h11, w31.y, ov[1][1]));
                ov[1][2] = fmaf(h10, w30.z, fmaf(h11, w31.z, ov[1][2]));
                ov[1][3] = fmaf(h10, w30.w, fmaf(h11, w31.w, ov[1][3]));
            }
            #pragma unroll
            for (int h = 0; h < 2; ++h)
                #pragma unroll
                for (int o = 0; o < 4; ++o) {
                    float v = ov[h][o];
                    v += __shfl_xor_sync(0xFFFFFFFF, v, 1);
                    v += __shfl_xor_sync(0xFFFFFFFF, v, 2);
                    ov[h][o] = v;
                }
            if (t4 == 0) {
                redc[wid * 32 + mt * 16 + g]     = make_float4(ov[0][0], ov[0][1], ov[0][2], ov[0][3]);
                redc[wid * 32 + mt * 16 + 8 + g] = make_float4(ov[1][0], ov[1][1], ov[1][2], ov[1][3]);
            }
        }
        __syncthreads();   // single barrier per iteration

        {
            const float4 r = redc[tid];
            const int it = TILE_AT(k);
            const int jt = it & 3;
            const int i  = (it >> 2) & (ID - 1);
            const int b  = it >> 11;
            const long base = ((long)(b * 4) * ID + i) * JD + jt * MROWS + tid;
            const long os   = (long)ID * JD;
            out[base]          = r.x + sb3[0];
            out[base + os]     = r.y + sb3[1];
            out[base + 2 * os] = r.z + sb3[2];
            out[base + 3 * os] = r.w + sb3[3];
        }
    }
}

extern "C" void kernel_launch(void* const* d_in, const int* in_sizes, int n_in,
                              void* d_out, int out_size)
{
    const float* grid_q  = (const float*)d_in[0];
    const float* grid_kv = (const float*)d_in[1];
    const float* W1      = (const float*)d_in[2];
    const float* b1      = (const float*)d_in[3];
    const float* W2      = (const float*)d_in[4];
    const float* b2      = (const float*)d_in[5];
    const float* W3      = (const float*)d_in[6];
    const float* b3      = (const float*)d_in[7];
    float* out = (float*)d_out;

    prep_w2<<<DD * DD / 256, 256>>>(W2);

    cudaFuncSetAttribute(crpb_kernel,
                         cudaFuncAttributeMaxDynamicSharedMemorySize, SMEM_BYTES);
    crpb_kernel<<<GRIDSZ, NTHREADS, SMEM_BYTES>>>(
        grid_q, grid_kv, W1, b1, b2, W3, b3, out);
}